// round 12
// baseline (speedup 1.0000x reference)
#include <cuda_runtime.h>
#include <cstdint>

// PCEN, TWO consecutive rows per CTA (grid = 4096), 64KB dynamic smem.
// Both 32KB row loads issued at CTA start (2 mbarriers); rows processed
// sequentially; ONE 64KB bulk store covers both rows (contiguous in out)
// -> doubled HBM write-burst length (confirmed lever from R11).
// 3 CTAs/SM resident. L2 evict_first hints. EMA in w-scaled space;
// pass-2 specialized on warp-uniform rhalf.
//   ema_t = w*x_t + (1-w)*ema_{t-1}, ema_0 = x_0   (affine block scan, exact)
//   out   = (x/(FLOOR+ema)^a + d)^(1/root) - d^(1/root)

constexpr int      kT        = 8000;
constexpr int      kChunk    = 25;            // 320*25 = 8000; 25 coprime 32 -> no bank conflicts
constexpr int      kThreads  = 320;
constexpr int      kWarps    = kThreads / 32; // 10
constexpr float    kFloor    = 1e-6f;
constexpr unsigned kRowBytes = kT * 4;        // 32000
constexpr unsigned kPairBytes = 2 * kRowBytes; // 64000

__device__ __forceinline__ uint32_t s2u(const void* p) {
    return (uint32_t)__cvta_generic_to_shared(p);
}

__device__ __forceinline__ float sqrt_apx(float v) {
    float r;
    asm("sqrt.approx.f32 %0, %1;" : "=f"(r) : "f"(v));
    return r;
}

__device__ __forceinline__ float rcp_apx(float v) {
    float r;
    asm("rcp.approx.f32 %0, %1;" : "=f"(r) : "f"(v));
    return r;
}

__device__ __forceinline__ uint64_t evict_first_policy() {
    uint64_t pol;
    asm("createpolicy.fractional.L2::evict_first.b64 %0, 1.0;" : "=l"(pol));
    return pol;
}

__device__ __forceinline__ void bulk_load_hint(uint32_t dst_smem, const void* src_gmem,
                                               uint32_t bytes, uint32_t mbar, uint64_t pol) {
    asm volatile(
        "cp.async.bulk.shared::cta.global.mbarrier::complete_tx::bytes.L2::cache_hint"
        " [%0], [%1], %2, [%3], %4;"
        :: "r"(dst_smem), "l"(src_gmem), "r"(bytes), "r"(mbar), "l"(pol) : "memory");
}

__device__ __forceinline__ void mbar_expect_tx(uint32_t mbar, uint32_t bytes) {
    asm volatile("mbarrier.arrive.expect_tx.shared::cta.b64 _, [%0], %1;"
                 :: "r"(mbar), "r"(bytes) : "memory");
}

__device__ __forceinline__ void mbar_wait(uint32_t mbar, uint32_t phase) {
    asm volatile(
        "{\n\t.reg .pred P;\n"
        "W_%=:\n\t"
        "mbarrier.try_wait.parity.acquire.cta.shared::cta.b64 P, [%0], %1, 0x989680;\n\t"
        "@!P bra W_%=;\n\t}"
        :: "r"(mbar), "r"(phase) : "memory");
}

__global__ void __launch_bounds__(kThreads, 3)
pcen_kernel(const float* __restrict__ x,
            const float* __restrict__ alpha,
            const float* __restrict__ delta,
            const float* __restrict__ root,
            const float* __restrict__ ew,
            float* __restrict__ out,
            int C)
{
    extern __shared__ float smem[];                // 2 * kT floats = 64000 B
    __shared__ __align__(8) unsigned long long mbar[2];
    __shared__ float sA[kWarps], sB[kWarps];

    const int tid   = threadIdx.x;
    const int lane  = tid & 31;
    const int wid   = tid >> 5;
    const int row0  = blockIdx.x * 2;

    const uint64_t pol = evict_first_policy();

    // kick off BOTH row loads ASAP (64KB in flight per CTA)
    if (tid == 0) {
        const float* src = x + (size_t)row0 * kT;
        #pragma unroll
        for (int rr = 0; rr < 2; ++rr) {
            const uint32_t mb = s2u(&mbar[rr]);
            asm volatile("mbarrier.init.shared::cta.b64 [%0], 1;" :: "r"(mb) : "memory");
            mbar_expect_tx(mb, kRowBytes);
            bulk_load_hint(s2u(smem + rr * kT), src + rr * kT, kRowBytes, mb, pol);
        }
    }
    __syncthreads();   // publish mbar init

    const int off = tid * kChunk;

    #pragma unroll
    for (int rr = 0; rr < 2; ++rr) {
        float* sx = smem + rr * kT;
        const int row = row0 + rr;

        // per-row params (warp-uniform); overlap the load wait
        const int   c  = row % C;
        const float w  = fminf(fmaxf(ew[c], 0.0f), 1.0f);
        const float q  = 1.0f - w;
        const float a  = fminf(alpha[c], 1.0f);
        const float d  = delta[c];
        const float r  = 1.0f / fmaxf(root[c], 1.0f);
        const bool  rhalf = (r == 0.5f);
        const float dr = rhalf ? sqrt_apx(d) : __powf(d, r);
        const float na = -a;
        const float winv = rcp_apx(fmaxf(w, 1e-30f));   // s-space: s = ema / w

        // wait for this row's data
        mbar_wait(s2u(&mbar[rr]), 0);

        // pass 1: per-thread affine reduce over the 25-element chunk (s-space)
        float b = 0.0f;
        #pragma unroll
        for (int k = 0; k < kChunk; ++k)
            b = fmaf(q, b, sx[off + k]);
        const float q2 = q*q, q4 = q2*q2, q8 = q4*q4, q16 = q8*q8;
        float A = q16 * q8 * q;   // q^25

        // warp inclusive scan of (A,b)
        #pragma unroll
        for (int s = 1; s < 32; s <<= 1) {
            float Ap = __shfl_up_sync(0xffffffffu, A, s);
            float bp = __shfl_up_sync(0xffffffffu, b, s);
            if (lane >= s) { b = fmaf(A, bp, b); A *= Ap; }
        }
        if (lane == 31) { sA[wid] = A; sB[wid] = b; }
        __syncthreads();

        // every warp redundantly scans the 10 warp aggregates (single barrier)
        float Aw = (lane < kWarps) ? sA[lane] : 1.0f;
        float bw = (lane < kWarps) ? sB[lane] : 0.0f;
        #pragma unroll
        for (int s = 1; s < 16; s <<= 1) {
            float Ap = __shfl_up_sync(0xffffffffu, Aw, s);
            float bp = __shfl_up_sync(0xffffffffu, bw, s);
            if (lane >= s) { bw = fmaf(Aw, bp, bw); Aw *= Ap; }
        }
        const int src = (wid > 0) ? (wid - 1) : 0;
        float ApX = __shfl_sync(0xffffffffu, Aw, src);
        float bpX = __shfl_sync(0xffffffffu, bw, src);
        if (wid == 0) { ApX = 1.0f; bpX = 0.0f; }

        // thread-exclusive prefix within warp, composed with warp prefix
        float Ai = __shfl_up_sync(0xffffffffu, A, 1);
        float bi = __shfl_up_sync(0xffffffffu, b, 1);
        if (lane == 0) { Ai = 1.0f; bi = 0.0f; }
        const float Aex = Ai * ApX;
        const float bex = fmaf(Ai, bpX, bi);
        const float s0  = sx[0] * winv;       // s-space init (ema_0 = x0)
        float acc = fmaf(Aex, s0, bex);       // exact carry (s-space) into this chunk

        // pass 2: EMA recompute (s-space) + pointwise PCEN, specialized on rhalf
        if (rhalf) {
            #pragma unroll
            for (int k = 0; k < kChunk; ++k) {
                const float xv = sx[off + k];
                acc = fmaf(q, acc, xv);                        // s_t
                const float v = fmaf(w, acc, kFloor);          // FLOOR + ema_t
                const float p = __powf(v, na);                 // lg2 + mul + ex2
                const float u = fmaf(xv, p, d);
                sx[off + k] = sqrt_apx(u) - dr;                // 1 MUFU
            }
        } else {
            #pragma unroll
            for (int k = 0; k < kChunk; ++k) {
                const float xv = sx[off + k];
                acc = fmaf(q, acc, xv);
                const float v = fmaf(w, acc, kFloor);
                const float p = __powf(v, na);
                const float u = fmaf(xv, p, d);
                sx[off + k] = __powf(u, r) - dr;
            }
        }

        // end-of-row barrier: orders pass-2 smem writes before the combined
        // store AND protects sA/sB reuse by the next row's scan.
        __syncthreads();
    }

    // single 64KB bulk store covering BOTH rows (contiguous in out)
    if (tid == 0) {
        asm volatile("fence.proxy.async.shared::cta;" ::: "memory");
        asm volatile(
            "cp.async.bulk.global.shared::cta.bulk_group.L2::cache_hint [%0], [%1], %2, %3;"
            :: "l"(out + (size_t)row0 * kT), "r"(s2u(smem)), "r"(kPairBytes), "l"(pol)
            : "memory");
        asm volatile("cp.async.bulk.commit_group;" ::: "memory");
        // smem must stay valid until the store has read it
        asm volatile("cp.async.bulk.wait_group.read 0;" ::: "memory");
    }
}

extern "C" void kernel_launch(void* const* d_in, const int* in_sizes, int n_in,
                              void* d_out, int out_size)
{
    const float* x     = (const float*)d_in[0];
    const float* alpha = (const float*)d_in[1];
    const float* delta = (const float*)d_in[2];
    const float* root  = (const float*)d_in[3];
    const float* ew    = (const float*)d_in[4];
    float* out = (float*)d_out;

    const int C    = in_sizes[1];            // 64
    const int rows = in_sizes[0] / kT;       // 8192

    const unsigned smemBytes = kPairBytes;   // 64000
    static bool configured = false;
    if (!configured) {
        cudaFuncSetAttribute(pcen_kernel,
                             cudaFuncAttributeMaxDynamicSharedMemorySize, smemBytes);
        cudaFuncSetAttribute(pcen_kernel,
                             cudaFuncAttributePreferredSharedMemoryCarveout, 100);
        configured = true;
    }

    pcen_kernel<<<rows / 2, kThreads, smemBytes>>>(x, alpha, delta, root, ew, out, C);
}

// round 13
// speedup vs baseline: 1.0214x; 1.0214x over previous
#include <cuda_runtime.h>
#include <cstdint>

// PCEN, 1 row per CTA (grid = 8192), 6 CTAs/SM (the measured occupancy
// optimum). SINGLE 32KB bulk load (one long read burst) and SINGLE 32KB
// bulk store (one long write burst) per CTA — long same-direction HBM
// streaks minimize R/W turnaround overhead (lever confirmed in R11;
// R12 showed bursts must not be bought with occupancy).
// L2 evict_first hints. EMA in w-scaled space (s = ema/w); pass-2
// specialized on warp-uniform rhalf.
//   ema_t = w*x_t + (1-w)*ema_{t-1}, ema_0 = x_0   (affine block scan, exact)
//   out   = (x/(FLOOR+ema)^a + d)^(1/root) - d^(1/root)

constexpr int      kT        = 8000;
constexpr int      kChunk    = 25;            // 320*25 = 8000; 25 coprime 32 -> no bank conflicts
constexpr int      kThreads  = 320;
constexpr int      kWarps    = kThreads / 32; // 10
constexpr float    kFloor    = 1e-6f;
constexpr unsigned kRowBytes = kT * 4;        // 32000

__device__ __forceinline__ uint32_t s2u(const void* p) {
    return (uint32_t)__cvta_generic_to_shared(p);
}

__device__ __forceinline__ float sqrt_apx(float v) {
    float r;
    asm("sqrt.approx.f32 %0, %1;" : "=f"(r) : "f"(v));
    return r;
}

__device__ __forceinline__ float rcp_apx(float v) {
    float r;
    asm("rcp.approx.f32 %0, %1;" : "=f"(r) : "f"(v));
    return r;
}

__device__ __forceinline__ uint64_t evict_first_policy() {
    uint64_t pol;
    asm("createpolicy.fractional.L2::evict_first.b64 %0, 1.0;" : "=l"(pol));
    return pol;
}

__device__ __forceinline__ void bulk_load_hint(uint32_t dst_smem, const void* src_gmem,
                                               uint32_t bytes, uint32_t mbar, uint64_t pol) {
    asm volatile(
        "cp.async.bulk.shared::cta.global.mbarrier::complete_tx::bytes.L2::cache_hint"
        " [%0], [%1], %2, [%3], %4;"
        :: "r"(dst_smem), "l"(src_gmem), "r"(bytes), "r"(mbar), "l"(pol) : "memory");
}

__device__ __forceinline__ void mbar_expect_tx(uint32_t mbar, uint32_t bytes) {
    asm volatile("mbarrier.arrive.expect_tx.shared::cta.b64 _, [%0], %1;"
                 :: "r"(mbar), "r"(bytes) : "memory");
}

__device__ __forceinline__ void mbar_wait(uint32_t mbar, uint32_t phase) {
    asm volatile(
        "{\n\t.reg .pred P;\n"
        "W_%=:\n\t"
        "mbarrier.try_wait.parity.acquire.cta.shared::cta.b64 P, [%0], %1, 0x989680;\n\t"
        "@!P bra W_%=;\n\t}"
        :: "r"(mbar), "r"(phase) : "memory");
}

__global__ void __launch_bounds__(kThreads, 6)
pcen_kernel(const float* __restrict__ x,
            const float* __restrict__ alpha,
            const float* __restrict__ delta,
            const float* __restrict__ root,
            const float* __restrict__ ew,
            float* __restrict__ out,
            int C)
{
    __shared__ float sx[kT];
    __shared__ __align__(8) unsigned long long mbar;
    __shared__ float sA[kWarps], sB[kWarps];

    const int tid  = threadIdx.x;
    const int lane = tid & 31;
    const int wid  = tid >> 5;
    const int row  = blockIdx.x;

    const uint64_t pol = evict_first_policy();

    // kick off the full-row load ASAP (one long 32KB read burst)
    if (tid == 0) {
        const uint32_t mb = s2u(&mbar);
        asm volatile("mbarrier.init.shared::cta.b64 [%0], 1;" :: "r"(mb) : "memory");
        mbar_expect_tx(mb, kRowBytes);
        bulk_load_hint(s2u(sx), x + (size_t)row * kT, kRowBytes, mb, pol);
    }

    // per-row params (warp-uniform); overlaps the bulk-load latency
    const int   c  = row % C;
    const float w  = fminf(fmaxf(ew[c], 0.0f), 1.0f);
    const float q  = 1.0f - w;
    const float a  = fminf(alpha[c], 1.0f);
    const float d  = delta[c];
    const float r  = 1.0f / fmaxf(root[c], 1.0f);
    const bool  rhalf = (r == 0.5f);
    const float dr = rhalf ? sqrt_apx(d) : __powf(d, r);
    const float na = -a;
    const float winv = rcp_apx(fmaxf(w, 1e-30f));   // s-space: s = ema / w

    // publish mbar init, then wait for the row
    __syncthreads();
    mbar_wait(s2u(&mbar), 0);

    const int off = tid * kChunk;

    // pass 1: per-thread affine reduce over the 25-element chunk (s-space)
    float b = 0.0f;
    #pragma unroll
    for (int k = 0; k < kChunk; ++k)
        b = fmaf(q, b, sx[off + k]);
    const float q2 = q*q, q4 = q2*q2, q8 = q4*q4, q16 = q8*q8;
    float A = q16 * q8 * q;   // q^25

    // warp inclusive scan of (A,b)
    #pragma unroll
    for (int s = 1; s < 32; s <<= 1) {
        float Ap = __shfl_up_sync(0xffffffffu, A, s);
        float bp = __shfl_up_sync(0xffffffffu, b, s);
        if (lane >= s) { b = fmaf(A, bp, b); A *= Ap; }
    }
    if (lane == 31) { sA[wid] = A; sB[wid] = b; }
    __syncthreads();

    // every warp redundantly scans the 10 warp aggregates (single barrier)
    float Aw = (lane < kWarps) ? sA[lane] : 1.0f;
    float bw = (lane < kWarps) ? sB[lane] : 0.0f;
    #pragma unroll
    for (int s = 1; s < 16; s <<= 1) {
        float Ap = __shfl_up_sync(0xffffffffu, Aw, s);
        float bp = __shfl_up_sync(0xffffffffu, bw, s);
        if (lane >= s) { bw = fmaf(Aw, bp, bw); Aw *= Ap; }
    }
    const int src = (wid > 0) ? (wid - 1) : 0;
    float ApX = __shfl_sync(0xffffffffu, Aw, src);
    float bpX = __shfl_sync(0xffffffffu, bw, src);
    if (wid == 0) { ApX = 1.0f; bpX = 0.0f; }

    // thread-exclusive prefix within warp, composed with warp prefix
    float Ai = __shfl_up_sync(0xffffffffu, A, 1);
    float bi = __shfl_up_sync(0xffffffffu, b, 1);
    if (lane == 0) { Ai = 1.0f; bi = 0.0f; }
    const float Aex = Ai * ApX;
    const float bex = fmaf(Ai, bpX, bi);
    const float s0  = sx[0] * winv;       // s-space init (ema_0 = x0)
    float acc = fmaf(Aex, s0, bex);       // exact carry (s-space) into this chunk

    // pass 2: EMA recompute (s-space) + pointwise PCEN, specialized on rhalf
    if (rhalf) {
        #pragma unroll
        for (int k = 0; k < kChunk; ++k) {
            const float xv = sx[off + k];
            acc = fmaf(q, acc, xv);                        // s_t
            const float v = fmaf(w, acc, kFloor);          // FLOOR + ema_t
            const float p = __powf(v, na);                 // lg2 + mul + ex2
            const float u = fmaf(xv, p, d);
            sx[off + k] = sqrt_apx(u) - dr;                // 1 MUFU
        }
    } else {
        #pragma unroll
        for (int k = 0; k < kChunk; ++k) {
            const float xv = sx[off + k];
            acc = fmaf(q, acc, xv);
            const float v = fmaf(w, acc, kFloor);
            const float p = __powf(v, na);
            const float u = fmaf(xv, p, d);
            sx[off + k] = __powf(u, r) - dr;
        }
    }

    // single full-row bulk store: one long 32KB write burst per CTA
    __syncthreads();
    if (tid == 0) {
        asm volatile("fence.proxy.async.shared::cta;" ::: "memory");
        asm volatile(
            "cp.async.bulk.global.shared::cta.bulk_group.L2::cache_hint [%0], [%1], %2, %3;"
            :: "l"(out + (size_t)row * kT), "r"(s2u(sx)), "r"(kRowBytes), "l"(pol)
            : "memory");
        asm volatile("cp.async.bulk.commit_group;" ::: "memory");
        // smem must stay valid until the store has read it
        asm volatile("cp.async.bulk.wait_group.read 0;" ::: "memory");
    }
}

extern "C" void kernel_launch(void* const* d_in, const int* in_sizes, int n_in,
                              void* d_out, int out_size)
{
    const float* x     = (const float*)d_in[0];
    const float* alpha = (const float*)d_in[1];
    const float* delta = (const float*)d_in[2];
    const float* root  = (const float*)d_in[3];
    const float* ew    = (const float*)d_in[4];
    float* out = (float*)d_out;

    const int C    = in_sizes[1];            // 64
    const int rows = in_sizes[0] / kT;       // 8192

    static bool configured = false;
    if (!configured) {
        cudaFuncSetAttribute(pcen_kernel,
                             cudaFuncAttributePreferredSharedMemoryCarveout, 100);
        configured = true;
    }

    pcen_kernel<<<rows, kThreads>>>(x, alpha, delta, root, ew, out, C);
}

// round 14
// speedup vs baseline: 1.0302x; 1.0086x over previous
#include <cuda_runtime.h>
#include <cstdint>

// PCEN — FINAL configuration (R11, best measured: 81.9us wall / 74.5us ncu,
// DRAM 79%, 6.26 TB/s mixed-stream ~ the HBM turnaround-limited optimum).
//
// Structure (each element the measured winner of both directions probed):
//  * 1 row per CTA, grid = B*C = 8192, 320 threads, 6 CTAs/SM resident.
//  * Row loaded as TWO 16KB cp.async.bulk copies with separate mbarriers;
//    warps 0-4 wait only on half 0, warps 5-9 only on half 1 (reads benefit
//    from transfer parallelism; R13 showed a single 32KB read is worse).
//  * SINGLE 32KB bulk store per CTA (writes benefit from long bursts: R11
//    beat 10x3.2KB eager stores; R12 showed 64KB bursts lose to occupancy).
//  * L2 evict_first on loads and stores (pure streaming).
//  * EMA tracked in w-scaled space: s = ema/w -> s = fma(q, s, x),
//    FLOOR+ema = fma(w, s, FLOOR).
//  * Exact affine block scan (thread reduce -> warp scan -> redundant
//    cross-warp scan, one barrier) — bitwise-stable vs reference scan.
//  * Pass-2 specialized on warp-uniform rhalf (root==2 -> sqrt.approx).
//   ema_t = w*x_t + (1-w)*ema_{t-1}, ema_0 = x_0
//   out   = (x/(FLOOR+ema)^a + d)^(1/root) - d^(1/root)

constexpr int      kT         = 8000;
constexpr int      kChunk     = 25;            // 320*25 = 8000; 25 coprime 32 -> no bank conflicts
constexpr int      kThreads   = 320;
constexpr int      kWarps     = kThreads / 32; // 10
constexpr float    kFloor     = 1e-6f;
constexpr int      kHalfElems = kT / 2;                    // 4000
constexpr unsigned kHalfBytes = kHalfElems * 4;            // 16000
constexpr unsigned kRowBytes  = kT * 4;                    // 32000

__device__ __forceinline__ uint32_t s2u(const void* p) {
    return (uint32_t)__cvta_generic_to_shared(p);
}

__device__ __forceinline__ float sqrt_apx(float v) {
    float r;
    asm("sqrt.approx.f32 %0, %1;" : "=f"(r) : "f"(v));
    return r;
}

__device__ __forceinline__ float rcp_apx(float v) {
    float r;
    asm("rcp.approx.f32 %0, %1;" : "=f"(r) : "f"(v));
    return r;
}

__device__ __forceinline__ uint64_t evict_first_policy() {
    uint64_t pol;
    asm("createpolicy.fractional.L2::evict_first.b64 %0, 1.0;" : "=l"(pol));
    return pol;
}

__device__ __forceinline__ void bulk_load_hint(uint32_t dst_smem, const void* src_gmem,
                                               uint32_t bytes, uint32_t mbar, uint64_t pol) {
    asm volatile(
        "cp.async.bulk.shared::cta.global.mbarrier::complete_tx::bytes.L2::cache_hint"
        " [%0], [%1], %2, [%3], %4;"
        :: "r"(dst_smem), "l"(src_gmem), "r"(bytes), "r"(mbar), "l"(pol) : "memory");
}

__device__ __forceinline__ void mbar_expect_tx(uint32_t mbar, uint32_t bytes) {
    asm volatile("mbarrier.arrive.expect_tx.shared::cta.b64 _, [%0], %1;"
                 :: "r"(mbar), "r"(bytes) : "memory");
}

__device__ __forceinline__ void mbar_wait(uint32_t mbar, uint32_t phase) {
    asm volatile(
        "{\n\t.reg .pred P;\n"
        "W_%=:\n\t"
        "mbarrier.try_wait.parity.acquire.cta.shared::cta.b64 P, [%0], %1, 0x989680;\n\t"
        "@!P bra W_%=;\n\t}"
        :: "r"(mbar), "r"(phase) : "memory");
}

__global__ void __launch_bounds__(kThreads, 6)
pcen_kernel(const float* __restrict__ x,
            const float* __restrict__ alpha,
            const float* __restrict__ delta,
            const float* __restrict__ root,
            const float* __restrict__ ew,
            float* __restrict__ out,
            int C)
{
    __shared__ float sx[kT];
    __shared__ __align__(8) unsigned long long mbar[2];
    __shared__ float sA[kWarps], sB[kWarps];

    const int tid  = threadIdx.x;
    const int lane = tid & 31;
    const int wid  = tid >> 5;
    const int row  = blockIdx.x;

    const uint64_t pol = evict_first_policy();

    // kick off both half-row loads ASAP
    if (tid == 0) {
        const uint32_t mb0 = s2u(&mbar[0]);
        const uint32_t mb1 = s2u(&mbar[1]);
        asm volatile("mbarrier.init.shared::cta.b64 [%0], 1;" :: "r"(mb0) : "memory");
        asm volatile("mbarrier.init.shared::cta.b64 [%0], 1;" :: "r"(mb1) : "memory");
        const float* src = x + (size_t)row * kT;
        mbar_expect_tx(mb0, kHalfBytes);
        bulk_load_hint(s2u(sx), src, kHalfBytes, mb0, pol);
        mbar_expect_tx(mb1, kHalfBytes);
        bulk_load_hint(s2u(sx + kHalfElems), src + kHalfElems, kHalfBytes, mb1, pol);
    }

    // per-row params (warp-uniform); overlaps the bulk-load latency
    const int   c  = row % C;
    const float w  = fminf(fmaxf(ew[c], 0.0f), 1.0f);
    const float q  = 1.0f - w;
    const float a  = fminf(alpha[c], 1.0f);
    const float d  = delta[c];
    const float r  = 1.0f / fmaxf(root[c], 1.0f);
    const bool  rhalf = (r == 0.5f);
    const float dr = rhalf ? sqrt_apx(d) : __powf(d, r);
    const float na = -a;
    const float winv = rcp_apx(fmaxf(w, 1e-30f));   // s-space: s = ema / w

    // make mbar init visible to all threads, then wait only for OUR half
    __syncthreads();
    mbar_wait(s2u(&mbar[wid < (kWarps / 2) ? 0 : 1]), 0);

    const int off = tid * kChunk;

    // pass 1: per-thread affine reduce over the 25-element chunk (s-space)
    float b = 0.0f;
    #pragma unroll
    for (int k = 0; k < kChunk; ++k)
        b = fmaf(q, b, sx[off + k]);
    const float q2 = q*q, q4 = q2*q2, q8 = q4*q4, q16 = q8*q8;
    float A = q16 * q8 * q;   // q^25

    // warp inclusive scan of (A,b)
    #pragma unroll
    for (int s = 1; s < 32; s <<= 1) {
        float Ap = __shfl_up_sync(0xffffffffu, A, s);
        float bp = __shfl_up_sync(0xffffffffu, b, s);
        if (lane >= s) { b = fmaf(A, bp, b); A *= Ap; }
    }
    if (lane == 31) { sA[wid] = A; sB[wid] = b; }
    __syncthreads();

    // every warp redundantly scans the 10 warp aggregates (single barrier)
    float Aw = (lane < kWarps) ? sA[lane] : 1.0f;
    float bw = (lane < kWarps) ? sB[lane] : 0.0f;
    #pragma unroll
    for (int s = 1; s < 16; s <<= 1) {
        float Ap = __shfl_up_sync(0xffffffffu, Aw, s);
        float bp = __shfl_up_sync(0xffffffffu, bw, s);
        if (lane >= s) { bw = fmaf(Aw, bp, bw); Aw *= Ap; }
    }
    const int src = (wid > 0) ? (wid - 1) : 0;
    float ApX = __shfl_sync(0xffffffffu, Aw, src);
    float bpX = __shfl_sync(0xffffffffu, bw, src);
    if (wid == 0) { ApX = 1.0f; bpX = 0.0f; }

    // thread-exclusive prefix within warp, composed with warp prefix
    float Ai = __shfl_up_sync(0xffffffffu, A, 1);
    float bi = __shfl_up_sync(0xffffffffu, b, 1);
    if (lane == 0) { Ai = 1.0f; bi = 0.0f; }
    const float Aex = Ai * ApX;
    const float bex = fmaf(Ai, bpX, bi);
    const float s0  = sx[0] * winv;       // s-space init (ema_0 = x0)
    float acc = fmaf(Aex, s0, bex);       // exact carry (s-space) into this chunk

    // pass 2: EMA recompute (s-space) + pointwise PCEN, specialized on rhalf
    if (rhalf) {
        #pragma unroll
        for (int k = 0; k < kChunk; ++k) {
            const float xv = sx[off + k];
            acc = fmaf(q, acc, xv);                        // s_t
            const float v = fmaf(w, acc, kFloor);          // FLOOR + ema_t
            const float p = __powf(v, na);                 // lg2 + mul + ex2
            const float u = fmaf(xv, p, d);
            sx[off + k] = sqrt_apx(u) - dr;                // 1 MUFU
        }
    } else {
        #pragma unroll
        for (int k = 0; k < kChunk; ++k) {
            const float xv = sx[off + k];
            acc = fmaf(q, acc, xv);
            const float v = fmaf(w, acc, kFloor);
            const float p = __powf(v, na);
            const float u = fmaf(xv, p, d);
            sx[off + k] = __powf(u, r) - dr;
        }
    }

    // single full-row bulk store: one long 32KB write burst per CTA
    __syncthreads();
    if (tid == 0) {
        asm volatile("fence.proxy.async.shared::cta;" ::: "memory");
        asm volatile(
            "cp.async.bulk.global.shared::cta.bulk_group.L2::cache_hint [%0], [%1], %2, %3;"
            :: "l"(out + (size_t)row * kT), "r"(s2u(sx)), "r"(kRowBytes), "l"(pol)
            : "memory");
        asm volatile("cp.async.bulk.commit_group;" ::: "memory");
        // smem must stay valid until the store has read it
        asm volatile("cp.async.bulk.wait_group.read 0;" ::: "memory");
    }
}

extern "C" void kernel_launch(void* const* d_in, const int* in_sizes, int n_in,
                              void* d_out, int out_size)
{
    const float* x     = (const float*)d_in[0];
    const float* alpha = (const float*)d_in[1];
    const float* delta = (const float*)d_in[2];
    const float* root  = (const float*)d_in[3];
    const float* ew    = (const float*)d_in[4];
    float* out = (float*)d_out;

    const int C    = in_sizes[1];            // 64
    const int rows = in_sizes[0] / kT;       // 8192

    static bool configured = false;
    if (!configured) {
        cudaFuncSetAttribute(pcen_kernel,
                             cudaFuncAttributePreferredSharedMemoryCarveout, 100);
        configured = true;
    }

    pcen_kernel<<<rows, kThreads>>>(x, alpha, delta, root, ew, out, C);
}